// round 10
// baseline (speedup 1.0000x reference)
#include <cuda_runtime.h>
#include <cuda_bf16.h>
#include <cstdint>

#define NB 256
#define NS 256
#define ND 256
#define NH 4
#define DH 64

// ---------------------------------------------------------------------------
// Device scratch (~34.5 MB total)
// ---------------------------------------------------------------------------
__device__ __nv_bfloat16 g_ctx[NB * NS * ND];   // parking for heads 0..2 ctx
__device__ __nv_bfloat16 g_Wqkv[3 * ND * ND];   // K-major: [mat][k][n] (0=Q,1=K,2=V)
__device__ __nv_bfloat16 g_Wo[ND * ND];         // K-major: [k][n]
__device__ int g_rank[NB];
__device__ int g_big[NB];

// ---------------------------------------------------------------------------
// PTX helpers
// ---------------------------------------------------------------------------
__device__ __forceinline__ uint32_t sptr(const void* p) {
    return static_cast<uint32_t>(__cvta_generic_to_shared(p));
}
__device__ __forceinline__ uint32_t swz(uint32_t off) {   // SW128: Swizzle<3,4,3>
    return off ^ ((off >> 3) & 0x70);
}
__device__ __forceinline__ void ldm_x4(uint32_t r[4], uint32_t a) {
    asm volatile("ldmatrix.sync.aligned.m8n8.x4.shared.b16 {%0,%1,%2,%3}, [%4];\n"
                 : "=r"(r[0]), "=r"(r[1]), "=r"(r[2]), "=r"(r[3]) : "r"(a));
}
__device__ __forceinline__ void ldm_x4t(uint32_t r[4], uint32_t a) {
    asm volatile("ldmatrix.sync.aligned.m8n8.x4.trans.shared.b16 {%0,%1,%2,%3}, [%4];\n"
                 : "=r"(r[0]), "=r"(r[1]), "=r"(r[2]), "=r"(r[3]) : "r"(a));
}
__device__ __forceinline__ void mma16816(float c[4], const uint32_t a[4], const uint32_t b[2]) {
    asm volatile(
        "mma.sync.aligned.m16n8k16.row.col.f32.bf16.bf16.f32 "
        "{%0,%1,%2,%3}, {%4,%5,%6,%7}, {%8,%9}, {%0,%1,%2,%3};\n"
        : "+f"(c[0]), "+f"(c[1]), "+f"(c[2]), "+f"(c[3])
        : "r"(a[0]), "r"(a[1]), "r"(a[2]), "r"(a[3]), "r"(b[0]), "r"(b[1]));
}
__device__ __forceinline__ uint32_t packbf(float x, float y) {
    __nv_bfloat162 t = __floats2bfloat162_rn(x, y);
    return *reinterpret_cast<uint32_t*>(&t);
}
__device__ __forceinline__ float fexp2(float x) {
    float y;
    asm("ex2.approx.ftz.f32 %0, %1;" : "=f"(y) : "f"(x));
    return y;
}
__device__ __forceinline__ void cpa16(uint32_t dst, const void* src) {
    asm volatile("cp.async.ca.shared.global [%0], [%1], 16;\n" :: "r"(dst), "l"(src));
}
__device__ __forceinline__ void cpcommit() {
    asm volatile("cp.async.commit_group;\n");
}
template <int N> __device__ __forceinline__ void cpwait() {
    asm volatile("cp.async.wait_group %0;\n" :: "n"(N));
}

// ---------------------------------------------------------------------------
// prep kernels
// ---------------------------------------------------------------------------
__global__ void prep_rank(const int* __restrict__ ids, int max_obj) {
    __shared__ int sh[NB];
    int t = threadIdx.x;
    sh[t] = ids[t];
    __syncthreads();
    int id = sh[t];
    int rank = 0, size = 0;
    #pragma unroll 8
    for (int j = 0; j < NB; j++) {
        int same = (sh[j] == id);
        size += same;
        rank += (j < t) ? same : 0;
    }
    g_rank[t] = (rank < max_obj) ? rank : (max_obj - 1);
    g_big[t]  = (size > 1);
}

__global__ void cast_weights(const float* __restrict__ Wq, const float* __restrict__ Wk,
                             const float* __restrict__ Wv, const float* __restrict__ Wo) {
    int i = blockIdx.x * 256 + threadIdx.x;
    int lin = i * 4;
    int mat = lin >> 16;
    int off = lin & 65535;
    const float* W = (mat == 0) ? Wq : ((mat == 1) ? Wk : ((mat == 2) ? Wv : Wo));
    float4 x = *reinterpret_cast<const float4*>(W + off);
    uint2 pk;
    pk.x = packbf(x.x, x.y);
    pk.y = packbf(x.z, x.w);
    __nv_bfloat16* dst = (mat < 3) ? (g_Wqkv + mat * 65536) : g_Wo;
    *reinterpret_cast<uint2*>(dst + off) = pk;
}

// ---------------------------------------------------------------------------
// Fully fused kernel: one block per batch b, 512 threads = 16 warps.
// smem = 7 x SW128 [256][64] bf16 tiles (32 KB each):
//   tiles 0..3: Es during head loop, then ctx (A of final GEMM)
//   tiles 4,5 : W_K/W_V -> K/V results, then Wo n-half during final GEMM
//   tile 6    : W_Q (prefetched for head h+1 during head h's attention)
// Final phase: out[b] = select(big, bs[b] + ctx[b] @ Wo + bo, bs[b]).
// ---------------------------------------------------------------------------
#define FUSED_SMEM (7 * 32768)

__global__ __launch_bounds__(512, 1) void fused_b(const float* __restrict__ bs,
                                                  const float* __restrict__ obj,
                                                  const float* __restrict__ scale,
                                                  const float* __restrict__ bq,
                                                  const float* __restrict__ bk,
                                                  const float* __restrict__ bv,
                                                  const float* __restrict__ bo,
                                                  float* __restrict__ out) {
    extern __shared__ char smraw[];
    const uint32_t smb = sptr(smraw);
    const int b = blockIdx.x;
    const int tid = threadIdx.x, lane = tid & 31, warp = tid >> 5;
    const int g = lane >> 2, tig = lane & 3;
    const int li = lane & 7, sel = lane >> 3;
    const float* src = bs + (size_t)b * NS * ND;

    // ---------------- Phase 1: build Es tiles 0..3 once --------------------
    {
        const int c = (tid & 63) << 2;
        char* tb = smraw + (c >> 6) * 32768;
        const int tcb = (c & 63) * 2;
        float4 av = *reinterpret_cast<const float4*>(&obj[g_rank[b] * ND + c]);
        float sc = scale[0];
        av.x *= sc; av.y *= sc; av.z *= sc; av.w *= sc;
        #pragma unroll 8
        for (int i = 0; i < 32; i++) {
            int row = i * 8 + (tid >> 6);
            float4 x = *reinterpret_cast<const float4*>(src + row * ND + c);
            uint2 pk;
            pk.x = packbf(x.x + av.x, x.y + av.y);
            pk.y = packbf(x.z + av.z, x.w + av.w);
            *reinterpret_cast<uint2*>(tb + swz(row * 128 + tcb)) = pk;
        }
    }

    const int mg = warp >> 1, ng = warp & 1;
    const float SC = 0.125f * 1.4426950408889634f;

    #pragma unroll 1
    for (int h = 0; h < NH; h++) {
        __syncthreads();

        // ---- stage weights: K,V always; Q only for h==0 (else prefetched) --
        if (h == 0) {
            #pragma unroll
            for (int i = 0; i < 12; i++) {
                int j = i * 512 + tid;
                int tmat = j >> 11;
                int rem = j & 2047;
                int r = rem >> 3;
                int cb = (rem & 7) * 16;
                int smat = tmat + 1; if (smat == 3) smat = 0;   // 0=Q,1=K,2=V
                cpa16(smb + (4 + tmat) * 32768 + swz(r * 128 + cb),
                      (const char*)g_Wqkv + smat * 131072 + r * 512 + h * 128 + cb);
            }
        } else {
            #pragma unroll
            for (int i = 0; i < 8; i++) {
                int j = i * 512 + tid;
                int tmat = j >> 11;                 // 0=K,1=V
                int rem = j & 2047;
                int r = rem >> 3;
                int cb = (rem & 7) * 16;
                cpa16(smb + (4 + tmat) * 32768 + swz(r * 128 + cb),
                      (const char*)g_Wqkv + (tmat + 1) * 131072 + r * 512 + h * 128 + cb);
            }
        }
        cpcommit();
        cpwait<0>();           // also drains the prior prefetch group
        __syncthreads();

        // ---- Pass 1: K & V GEMM. Warp tile M=32, N=64; ng -> K or V -------
        float acc[2][8][4];
        #pragma unroll
        for (int mi = 0; mi < 2; mi++)
            #pragma unroll
            for (int nj = 0; nj < 8; nj++)
                #pragma unroll
                for (int c = 0; c < 4; c++) acc[mi][nj][c] = 0.f;

        const uint32_t wtile = smb + (4 + ng) * 32768;
        #pragma unroll 1
        for (int ks = 0; ks < 16; ks++) {
            const int kq = ks >> 2;
            const int acb = (ks & 3) * 32 + (sel >> 1) * 16;
            uint32_t afr[2][4];
            ldm_x4(afr[0], smb + kq * 32768 + swz((mg * 32 + (sel & 1) * 8 + li) * 128 + acb));
            ldm_x4(afr[1], smb + kq * 32768 + swz((mg * 32 + 16 + (sel & 1) * 8 + li) * 128 + acb));
            #pragma unroll
            for (int njp = 0; njp < 4; njp++) {
                uint32_t b4[4];
                ldm_x4t(b4, wtile + swz((ks * 16 + (sel & 1) * 8 + li) * 128 +
                                        (2 * njp + (sel >> 1)) * 16));
                mma16816(acc[0][2 * njp],     afr[0], b4);
                mma16816(acc[1][2 * njp],     afr[1], b4);
                mma16816(acc[0][2 * njp + 1], afr[0], b4 + 2);
                mma16816(acc[1][2 * njp + 1], afr[1], b4 + 2);
            }
        }
        __syncthreads();   // all warps done reading W_K / W_V tiles

        // ---- epilogue: bias + overwrite tile 4/5 with K/V results ---------
        {
            const float* bias = (ng == 0) ? bk : bv;
            #pragma unroll
            for (int mi = 0; mi < 2; mi++)
                #pragma unroll
                for (int nj = 0; nj < 8; nj++) {
                    int col = nj * 8 + tig * 2;
                    float b0 = bias[h * DH + col], b1 = bias[h * DH + col + 1];
                    #pragma unroll
                    for (int p = 0; p < 2; p++) {
                        int row = mg * 32 + mi * 16 + p * 8 + g;
                        *reinterpret_cast<__nv_bfloat162*>(
                            smraw + (4 + ng) * 32768 + swz(row * 128 + col * 2)) =
                            __floats2bfloat162_rn(acc[mi][nj][p * 2] + b0,
                                                  acc[mi][nj][p * 2 + 1] + b1);
                    }
                }
        }

        // ---- Pass 2: Q GEMM. Warp tile M=16, N=64 (rows match attention) --
        float accQ[8][4];
        #pragma unroll
        for (int nj = 0; nj < 8; nj++)
            #pragma unroll
            for (int c = 0; c < 4; c++) accQ[nj][c] = 0.f;

        #pragma unroll 1
        for (int ks = 0; ks < 16; ks++) {
            const int kq = ks >> 2;
            const int acb = (ks & 3) * 32 + (sel >> 1) * 16;
            uint32_t afr[4];
            ldm_x4(afr, smb + kq * 32768 + swz((warp * 16 + (sel & 1) * 8 + li) * 128 + acb));
            #pragma unroll
            for (int njp = 0; njp < 4; njp++) {
                uint32_t b4[4];
                ldm_x4t(b4, smb + 6 * 32768 + swz((ks * 16 + (sel & 1) * 8 + li) * 128 +
                                                  (2 * njp + (sel >> 1)) * 16));
                mma16816(accQ[2 * njp],     afr, b4);
                mma16816(accQ[2 * njp + 1], afr, b4 + 2);
            }
        }
        // pack Q accumulators directly into A-fragments (bias folded)
        uint32_t qf[4][4];
        #pragma unroll
        for (int kd = 0; kd < 4; kd++) {
            float b0 = bq[h * DH + kd * 16 + tig * 2];
            float b1 = bq[h * DH + kd * 16 + tig * 2 + 1];
            float b2 = bq[h * DH + kd * 16 + 8 + tig * 2];
            float b3 = bq[h * DH + kd * 16 + 8 + tig * 2 + 1];
            qf[kd][0] = packbf(accQ[2 * kd][0] + b0, accQ[2 * kd][1] + b1);
            qf[kd][1] = packbf(accQ[2 * kd][2] + b0, accQ[2 * kd][3] + b1);
            qf[kd][2] = packbf(accQ[2 * kd + 1][0] + b2, accQ[2 * kd + 1][1] + b3);
            qf[kd][3] = packbf(accQ[2 * kd + 1][2] + b2, accQ[2 * kd + 1][3] + b3);
        }
        __syncthreads();   // K/V results visible; Es/Q-tile reads done

        // ---- prefetch under attention: next Q weights, or (last head)
        //      parked ctx of heads 0..2 into the now-dead Es tiles 0..2 -----
        if (h < NH - 1) {
            #pragma unroll
            for (int i = 0; i < 4; i++) {
                int j = i * 512 + tid;
                int r = j >> 3;
                int cb = (j & 7) * 16;
                cpa16(smb + 6 * 32768 + swz(r * 128 + cb),
                      (const char*)g_Wqkv + r * 512 + (h + 1) * 128 + cb);
            }
            cpcommit();
        } else {
            #pragma unroll
            for (int i = 0; i < 12; i++) {
                int j = i * 512 + tid;              // 6144 chunks: 3 ctx tiles
                int t = j >> 11;
                int rem = j & 2047;
                int r = rem >> 3;
                int cb = (rem & 7) * 16;
                cpa16(smb + t * 32768 + swz(r * 128 + cb),
                      (const char*)g_ctx + ((size_t)(b * NS + r)) * 512 + t * 128 + cb);
            }
            cpcommit();
        }

        // ---- flash attention (no-max softmax), M=16 rows per warp ---------
        float O[8][4];
        #pragma unroll
        for (int j = 0; j < 8; j++)
            #pragma unroll
            for (int c = 0; c < 4; c++) O[j][c] = 0.f;
        float lrow[2] = {0.f, 0.f};

        #pragma unroll 1
        for (int kc = 0; kc < 4; kc++) {
            float s[8][4];
            #pragma unroll
            for (int j = 0; j < 8; j++)
                #pragma unroll
                for (int c = 0; c < 4; c++) s[j][c] = 0.f;

            // S = Q K^T
            #pragma unroll
            for (int kd = 0; kd < 4; kd++)
                #pragma unroll
                for (int njp = 0; njp < 4; njp++) {
                    uint32_t b4[4];
                    ldm_x4(b4, smb + 4 * 32768 +
                           swz((kc * 64 + (2 * njp + (sel >> 1)) * 8 + li) * 128 +
                               kd * 32 + (sel & 1) * 16));
                    mma16816(s[2 * njp],     qf[kd], b4);
                    mma16816(s[2 * njp + 1], qf[kd], b4 + 2);
                }

            // exp + row sums
            #pragma unroll
            for (int rs = 0; rs < 2; rs++) {
                float sum = 0.f;
                #pragma unroll
                for (int nj = 0; nj < 8; nj++) {
                    float p0 = fexp2(s[nj][rs * 2] * SC);
                    float p1 = fexp2(s[nj][rs * 2 + 1] * SC);
                    s[nj][rs * 2] = p0;
                    s[nj][rs * 2 + 1] = p1;
                    sum += p0 + p1;
                }
                sum += __shfl_xor_sync(0xffffffffu, sum, 1);
                sum += __shfl_xor_sync(0xffffffffu, sum, 2);
                lrow[rs] += sum;
            }

            // O += P V
            #pragma unroll
            for (int kk = 0; kk < 4; kk++) {
                uint32_t pa[4];
                pa[0] = packbf(s[2 * kk][0],     s[2 * kk][1]);
                pa[1] = packbf(s[2 * kk][2],     s[2 * kk][3]);
                pa[2] = packbf(s[2 * kk + 1][0], s[2 * kk + 1][1]);
                pa[3] = packbf(s[2 * kk + 1][2], s[2 * kk + 1][3]);
                #pragma unroll
                for (int njp = 0; njp < 4; njp++) {
                    uint32_t b4[4];
                    ldm_x4t(b4, smb + 5 * 32768 +
                            swz((kc * 64 + kk * 16 + (sel & 1) * 8 + li) * 128 +
                                (2 * njp + (sel >> 1)) * 16));
                    mma16816(O[2 * njp],     pa, b4);
                    mma16816(O[2 * njp + 1], pa, b4 + 2);
                }
            }
        }

        // ---- ctx: heads 0..2 -> global parking; head 3 -> smem tile 3 -----
        if (h < NH - 1) {
            #pragma unroll
            for (int rs = 0; rs < 2; rs++) {
                float inv = 1.f / lrow[rs];
                int row = warp * 16 + rs * 8 + g;
                #pragma unroll
                for (int nj = 0; nj < 8; nj++) {
                    int col = nj * 8 + tig * 2;
                    *reinterpret_cast<__nv_bfloat162*>(
                        &g_ctx[((size_t)b * NS + row) * ND + h * DH + col]) =
                        __floats2bfloat162_rn(O[nj][rs * 2] * inv, O[nj][rs * 2 + 1] * inv);
                }
            }
        } else {
            #pragma unroll
            for (int rs = 0; rs < 2; rs++) {
                float inv = 1.f / lrow[rs];
                int row = warp * 16 + rs * 8 + g;
                #pragma unroll
                for (int nj = 0; nj < 8; nj++) {
                    int col = nj * 8 + tig * 2;
                    *reinterpret_cast<__nv_bfloat162*>(
                        smraw + 3 * 32768 + swz(row * 128 + col * 2)) =
                        __floats2bfloat162_rn(O[nj][rs * 2] * inv, O[nj][rs * 2 + 1] * inv);
                }
            }
        }
    }

    // ================= Final phase: out = bs + ctx @ Wo + bo ===============
    // ctx: tiles 0..3 (A, [256 rows][256 k]); Wo staged per n-half -> tiles 4,5
    const int big = g_big[b];
    #pragma unroll 1
    for (int half = 0; half < 2; half++) {
        __syncthreads();   // half0: attention + tile-3 writes done; half1: prior reads done
        #pragma unroll
        for (int i = 0; i < 8; i++) {
            int j = i * 512 + tid;
            int t = j >> 11;
            int rem = j & 2047;
            int r = rem >> 3;
            int cb = (rem & 7) * 16;
            cpa16(smb + (4 + t) * 32768 + swz(r * 128 + cb),
                  (const char*)g_Wo + r * 512 + half * 256 + t * 128 + cb);
        }
        cpcommit();
        cpwait<0>();       // half0: also drains the ctx-tile prefetch
        __syncthreads();

        float acc[2][8][4];
        #pragma unroll
        for (int mi = 0; mi < 2; mi++)
            #pragma unroll
            for (int nj = 0; nj < 8; nj++)
                #pragma unroll
                for (int c = 0; c < 4; c++) acc[mi][nj][c] = 0.f;

        const uint32_t wtile = smb + (4 + ng) * 32768;
        #pragma unroll 1
        for (int ks = 0; ks < 16; ks++) {
            const int kq = ks >> 2;
            const int acb = (ks & 3) * 32 + (sel >> 1) * 16;
            uint32_t afr[2][4];
            ldm_x4(afr[0], smb + kq * 32768 + swz((mg * 32 + (sel & 1) * 8 + li) * 128 + acb));
            ldm_x4(afr[1], smb + kq * 32768 + swz((mg * 32 + 16 + (sel & 1) * 8 + li) * 128 + acb));
            #pragma unroll
            for (int njp = 0; njp < 4; njp++) {
                uint32_t b4[4];
                ldm_x4t(b4, wtile + swz((ks * 16 + (sel & 1) * 8 + li) * 128 +
                                        (2 * njp + (sel >> 1)) * 16));
                mma16816(acc[0][2 * njp],     afr[0], b4);
                mma16816(acc[1][2 * njp],     afr[1], b4);
                mma16816(acc[0][2 * njp + 1], afr[0], b4 + 2);
                mma16816(acc[1][2 * njp + 1], afr[1], b4 + 2);
            }
        }

        // epilogue: residual + bias + group select, straight to out
        #pragma unroll
        for (int mi = 0; mi < 2; mi++)
            #pragma unroll
            for (int nj = 0; nj < 8; nj++)
                #pragma unroll
                for (int p = 0; p < 2; p++) {
                    int row = mg * 32 + mi * 16 + p * 8 + g;
                    int n = half * 128 + ng * 64 + nj * 8 + tig * 2;
                    int idx = (b * NS + row) * ND + n;
                    float2 base = *reinterpret_cast<const float2*>(&bs[idx]);
                    float2 o;
                    if (big) {
                        o.x = base.x + acc[mi][nj][p * 2]     + bo[n];
                        o.y = base.y + acc[mi][nj][p * 2 + 1] + bo[n + 1];
                    } else {
                        o = base;
                    }
                    *reinterpret_cast<float2*>(&out[idx]) = o;
                }
    }
}

// ---------------------------------------------------------------------------
// Launch
// ---------------------------------------------------------------------------
extern "C" void kernel_launch(void* const* d_in, const int* in_sizes, int n_in,
                              void* d_out, int out_size) {
    const float* bs    = (const float*)d_in[0];
    const int*   ids   = (const int*)d_in[1];
    const float* Wq    = (const float*)d_in[2];
    const float* Wk    = (const float*)d_in[3];
    const float* Wv    = (const float*)d_in[4];
    const float* Wo    = (const float*)d_in[5];
    const float* bq    = (const float*)d_in[6];
    const float* bk    = (const float*)d_in[7];
    const float* bv    = (const float*)d_in[8];
    const float* bo    = (const float*)d_in[9];
    const float* obj   = (const float*)d_in[10];
    const float* scale = (const float*)d_in[11];
    const int max_obj = in_sizes[10] / ND;

    static bool configured = false;
    if (!configured) {
        cudaFuncSetAttribute(fused_b, cudaFuncAttributeMaxDynamicSharedMemorySize, FUSED_SMEM);
        configured = true;
    }

    prep_rank<<<1, NB>>>(ids, max_obj);
    cast_weights<<<256, 256>>>(Wq, Wk, Wv, Wo);
    fused_b<<<NB, 512, FUSED_SMEM>>>(bs, obj, scale, bq, bk, bv, bo, (float*)d_out);
}

// round 12
// speedup vs baseline: 1.5672x; 1.5672x over previous
#include <cuda_runtime.h>
#include <cuda_bf16.h>
#include <cstdint>

#define NB 256
#define NS 256
#define ND 256
#define NH 4
#define DH 64

// ---------------------------------------------------------------------------
// Device scratch (~34.5 MB total)
// ---------------------------------------------------------------------------
__device__ __nv_bfloat16 g_ctx[NB * NS * ND];   // [b*s][d]
__device__ __nv_bfloat16 g_Wqkv[3 * ND * ND];   // K-major: [mat][k][n] (0=Q,1=K,2=V)
__device__ __nv_bfloat16 g_Wo[ND * ND];         // K-major: [k][n]

// ---------------------------------------------------------------------------
// PTX helpers
// ---------------------------------------------------------------------------
__device__ __forceinline__ uint32_t sptr(const void* p) {
    return static_cast<uint32_t>(__cvta_generic_to_shared(p));
}
__device__ __forceinline__ uint32_t swz(uint32_t off) {   // SW128: Swizzle<3,4,3>
    return off ^ ((off >> 3) & 0x70);
}
__device__ __forceinline__ void ldm_x4(uint32_t r[4], uint32_t a) {
    asm volatile("ldmatrix.sync.aligned.m8n8.x4.shared.b16 {%0,%1,%2,%3}, [%4];\n"
                 : "=r"(r[0]), "=r"(r[1]), "=r"(r[2]), "=r"(r[3]) : "r"(a));
}
__device__ __forceinline__ void ldm_x2(uint32_t r[2], uint32_t a) {
    asm volatile("ldmatrix.sync.aligned.m8n8.x2.shared.b16 {%0,%1}, [%2];\n"
                 : "=r"(r[0]), "=r"(r[1]) : "r"(a));
}
__device__ __forceinline__ void ldm_x4t(uint32_t r[4], uint32_t a) {
    asm volatile("ldmatrix.sync.aligned.m8n8.x4.trans.shared.b16 {%0,%1,%2,%3}, [%4];\n"
                 : "=r"(r[0]), "=r"(r[1]), "=r"(r[2]), "=r"(r[3]) : "r"(a));
}
__device__ __forceinline__ void ldm_x2t(uint32_t r[2], uint32_t a) {
    asm volatile("ldmatrix.sync.aligned.m8n8.x2.trans.shared.b16 {%0,%1}, [%2];\n"
                 : "=r"(r[0]), "=r"(r[1]) : "r"(a));
}
__device__ __forceinline__ void mma16816(float c[4], const uint32_t a[4], const uint32_t b[2]) {
    asm volatile(
        "mma.sync.aligned.m16n8k16.row.col.f32.bf16.bf16.f32 "
        "{%0,%1,%2,%3}, {%4,%5,%6,%7}, {%8,%9}, {%0,%1,%2,%3};\n"
        : "+f"(c[0]), "+f"(c[1]), "+f"(c[2]), "+f"(c[3])
        : "r"(a[0]), "r"(a[1]), "r"(a[2]), "r"(a[3]), "r"(b[0]), "r"(b[1]));
}
__device__ __forceinline__ uint32_t packbf(float x, float y) {
    __nv_bfloat162 t = __floats2bfloat162_rn(x, y);
    return *reinterpret_cast<uint32_t*>(&t);
}
__device__ __forceinline__ float fexp2(float x) {
    float y;
    asm("ex2.approx.ftz.f32 %0, %1;" : "=f"(y) : "f"(x));
    return y;
}
__device__ __forceinline__ void cpa16(uint32_t dst, const void* src) {
    asm volatile("cp.async.ca.shared.global [%0], [%1], 16;\n" :: "r"(dst), "l"(src));
}
__device__ __forceinline__ void cpcommit() {
    asm volatile("cp.async.commit_group;\n");
}
template <int N> __device__ __forceinline__ void cpwait() {
    asm volatile("cp.async.wait_group %0;\n" :: "n"(N));
}

// ---------------------------------------------------------------------------
// prep: weight cast (pure coalesced fp32 -> bf16, K-major layout kept)
// ---------------------------------------------------------------------------
__global__ void cast_weights(const float* __restrict__ Wq, const float* __restrict__ Wk,
                             const float* __restrict__ Wv, const float* __restrict__ Wo) {
    int i = blockIdx.x * 256 + threadIdx.x;
    int lin = i * 4;
    int mat = lin >> 16;
    int off = lin & 65535;
    const float* W = (mat == 0) ? Wq : ((mat == 1) ? Wk : ((mat == 2) ? Wv : Wo));
    float4 x = *reinterpret_cast<const float4*>(W + off);
    uint2 pk;
    pk.x = packbf(x.x, x.y);
    pk.y = packbf(x.z, x.w);
    __nv_bfloat16* dst = (mat < 3) ? (g_Wqkv + mat * 65536) : g_Wo;
    *reinterpret_cast<uint2*>(dst + off) = pk;
}

// ---------------------------------------------------------------------------
// Fused kernel (R8 config): one block per batch b, 512 threads = 16 warps.
// smem = 7 x SW128 [256][64] bf16 tiles (32 KB each):
//   tiles 0..3: Es ; tiles 4,5: W_K/W_V then K/V results; tile 6: W_Q
//   (prefetched for head h+1 during head h's attention phase).
// rank/gsize computed inline via ballot (no prep kernel).
// ---------------------------------------------------------------------------
#define FUSED_SMEM (7 * 32768)

__global__ __launch_bounds__(512, 1) void fused_b(const float* __restrict__ bs,
                                                  const int* __restrict__ ids,
                                                  const float* __restrict__ obj,
                                                  const float* __restrict__ scale,
                                                  const float* __restrict__ bq,
                                                  const float* __restrict__ bk,
                                                  const float* __restrict__ bv,
                                                  int max_obj) {
    extern __shared__ char smraw[];
    const uint32_t smb = sptr(smraw);
    const int b = blockIdx.x;
    const int tid = threadIdx.x, lane = tid & 31, warp = tid >> 5;
    const int g = lane >> 2, tig = lane & 3;
    const int li = lane & 7, sel = lane >> 3;
    const float* src = bs + (size_t)b * NS * ND;

    // ---------------- inline rank for this b (ballot reduce) ---------------
    __shared__ int s_rank;
    if (tid == 0) s_rank = 0;
    __syncthreads();
    if (tid < 256) {
        int idb = __ldg(&ids[b]);
        bool same_lt = (__ldg(&ids[tid]) == idb) && (tid < b);
        unsigned m = __ballot_sync(0xffffffffu, same_lt);
        if (lane == 0 && m) atomicAdd(&s_rank, __popc(m));
    }
    __syncthreads();
    const int rank = (s_rank < max_obj) ? s_rank : (max_obj - 1);

    // ---------------- Phase 1: build Es tiles 0..3 once --------------------
    {
        const int c = (tid & 63) << 2;
        char* tb = smraw + (c >> 6) * 32768;
        const int tcb = (c & 63) * 2;
        float4 av = *reinterpret_cast<const float4*>(&obj[rank * ND + c]);
        float sc = scale[0];
        av.x *= sc; av.y *= sc; av.z *= sc; av.w *= sc;
        #pragma unroll 8
        for (int i = 0; i < 32; i++) {
            int row = i * 8 + (tid >> 6);
            float4 x = *reinterpret_cast<const float4*>(src + row * ND + c);
            uint2 pk;
            pk.x = packbf(x.x + av.x, x.y + av.y);
            pk.y = packbf(x.z + av.z, x.w + av.w);
            *reinterpret_cast<uint2*>(tb + swz(row * 128 + tcb)) = pk;
        }
    }

    const int mg = warp >> 1, ng = warp & 1;     // KV pass: 8 m-groups x {K,V}
    const float SC = 0.125f * 1.4426950408889634f;

    #pragma unroll 1
    for (int h = 0; h < NH; h++) {
        __syncthreads();   // Es ready (h=0) / attention done with tiles 4,5 (h>0)

        // ---- stage weights: K,V always; Q only for h==0 (else prefetched) --
        if (h == 0) {
            #pragma unroll
            for (int i = 0; i < 12; i++) {
                int j = i * 512 + tid;
                int tmat = j >> 11;
                int rem = j & 2047;
                int r = rem >> 3;
                int cb = (rem & 7) * 16;
                int smat = tmat + 1; if (smat == 3) smat = 0;   // 0=Q,1=K,2=V
                cpa16(smb + (4 + tmat) * 32768 + swz(r * 128 + cb),
                      (const char*)g_Wqkv + smat * 131072 + r * 512 + h * 128 + cb);
            }
        } else {
            #pragma unroll
            for (int i = 0; i < 8; i++) {
                int j = i * 512 + tid;
                int tmat = j >> 11;                 // 0=K,1=V
                int rem = j & 2047;
                int r = rem >> 3;
                int cb = (rem & 7) * 16;
                cpa16(smb + (4 + tmat) * 32768 + swz(r * 128 + cb),
                      (const char*)g_Wqkv + (tmat + 1) * 131072 + r * 512 + h * 128 + cb);
            }
        }
        cpcommit();
        cpwait<0>();           // also drains the Q-prefetch group from last head
        __syncthreads();

        // ---- Pass 1: K & V GEMM. Warp tile M=32, N=64; ng -> K or V -------
        float acc[2][8][4];
        #pragma unroll
        for (int mi = 0; mi < 2; mi++)
            #pragma unroll
            for (int nj = 0; nj < 8; nj++)
                #pragma unroll
                for (int c = 0; c < 4; c++) acc[mi][nj][c] = 0.f;

        const uint32_t wtile = smb + (4 + ng) * 32768;
        #pragma unroll 1
        for (int ks = 0; ks < 16; ks++) {
            const int kq = ks >> 2;
            const int acb = (ks & 3) * 32 + (sel >> 1) * 16;
            uint32_t afr[2][4];
            ldm_x4(afr[0], smb + kq * 32768 + swz((mg * 32 + (sel & 1) * 8 + li) * 128 + acb));
            ldm_x4(afr[1], smb + kq * 32768 + swz((mg * 32 + 16 + (sel & 1) * 8 + li) * 128 + acb));
            #pragma unroll
            for (int njp = 0; njp < 4; njp++) {
                uint32_t b4[4];
                ldm_x4t(b4, wtile + swz((ks * 16 + (sel & 1) * 8 + li) * 128 +
                                        (2 * njp + (sel >> 1)) * 16));
                mma16816(acc[0][2 * njp],     afr[0], b4);
                mma16816(acc[1][2 * njp],     afr[1], b4);
                mma16816(acc[0][2 * njp + 1], afr[0], b4 + 2);
                mma16816(acc[1][2 * njp + 1], afr[1], b4 + 2);
            }
        }
        __syncthreads();   // all warps done reading W_K / W_V tiles

        // ---- epilogue: bias + overwrite tile 4/5 with K/V results ---------
        {
            const float* bias = (ng == 0) ? bk : bv;
            #pragma unroll
            for (int mi = 0; mi < 2; mi++)
                #pragma unroll
                for (int nj = 0; nj < 8; nj++) {
                    int col = nj * 8 + tig * 2;
                    float b0 = bias[h * DH + col], b1 = bias[h * DH + col + 1];
                    #pragma unroll
                    for (int p = 0; p < 2; p++) {
                        int row = mg * 32 + mi * 16 + p * 8 + g;
                        *reinterpret_cast<__nv_bfloat162*>(
                            smraw + (4 + ng) * 32768 + swz(row * 128 + col * 2)) =
                            __floats2bfloat162_rn(acc[mi][nj][p * 2] + b0,
                                                  acc[mi][nj][p * 2 + 1] + b1);
                    }
                }
        }

        // ---- Pass 2: Q GEMM. Warp tile M=16, N=64 (rows match attention) --
        float accQ[8][4];
        #pragma unroll
        for (int nj = 0; nj < 8; nj++)
            #pragma unroll
            for (int c = 0; c < 4; c++) accQ[nj][c] = 0.f;

        #pragma unroll 1
        for (int ks = 0; ks < 16; ks++) {
            const int kq = ks >> 2;
            const int acb = (ks & 3) * 32 + (sel >> 1) * 16;
            uint32_t afr[4];
            ldm_x4(afr, smb + kq * 32768 + swz((warp * 16 + (sel & 1) * 8 + li) * 128 + acb));
            #pragma unroll
            for (int njp = 0; njp < 4; njp++) {
                uint32_t b4[4];
                ldm_x4t(b4, smb + 6 * 32768 + swz((ks * 16 + (sel & 1) * 8 + li) * 128 +
                                                  (2 * njp + (sel >> 1)) * 16));
                mma16816(accQ[2 * njp],     afr, b4);
                mma16816(accQ[2 * njp + 1], afr, b4 + 2);
            }
        }
        // pack Q accumulators directly into A-fragments (bias folded)
        uint32_t qf[4][4];
        #pragma unroll
        for (int kd = 0; kd < 4; kd++) {
            float b0 = bq[h * DH + kd * 16 + tig * 2];
            float b1 = bq[h * DH + kd * 16 + tig * 2 + 1];
            float b2 = bq[h * DH + kd * 16 + 8 + tig * 2];
            float b3 = bq[h * DH + kd * 16 + 8 + tig * 2 + 1];
            qf[kd][0] = packbf(accQ[2 * kd][0] + b0, accQ[2 * kd][1] + b1);
            qf[kd][1] = packbf(accQ[2 * kd][2] + b0, accQ[2 * kd][3] + b1);
            qf[kd][2] = packbf(accQ[2 * kd + 1][0] + b2, accQ[2 * kd + 1][1] + b3);
            qf[kd][3] = packbf(accQ[2 * kd + 1][2] + b2, accQ[2 * kd + 1][3] + b3);
        }
        __syncthreads();   // K/V results visible; tile 6 reads done

        // ---- prefetch next head's Q weights into tile 6 (free now) --------
        if (h < NH - 1) {
            #pragma unroll
            for (int i = 0; i < 4; i++) {
                int j = i * 512 + tid;
                int r = j >> 3;
                int cb = (j & 7) * 16;
                cpa16(smb + 6 * 32768 + swz(r * 128 + cb),
                      (const char*)g_Wqkv + r * 512 + (h + 1) * 128 + cb);
            }
            cpcommit();
        }

        // ---- flash attention (no-max softmax), M=16 rows per warp ---------
        float O[8][4];
        #pragma unroll
        for (int j = 0; j < 8; j++)
            #pragma unroll
            for (int c = 0; c < 4; c++) O[j][c] = 0.f;
        float lrow[2] = {0.f, 0.f};

        #pragma unroll 1
        for (int kc = 0; kc < 4; kc++) {
            float s[8][4];
            #pragma unroll
            for (int j = 0; j < 8; j++)
                #pragma unroll
                for (int c = 0; c < 4; c++) s[j][c] = 0.f;

            // S = Q K^T  (K fragments: x4, two key-groups per instr)
            #pragma unroll
            for (int kd = 0; kd < 4; kd++)
                #pragma unroll
                for (int njp = 0; njp < 4; njp++) {
                    uint32_t b4[4];
                    ldm_x4(b4, smb + 4 * 32768 +
                           swz((kc * 64 + (2 * njp + (sel >> 1)) * 8 + li) * 128 +
                               kd * 32 + (sel & 1) * 16));
                    mma16816(s[2 * njp],     qf[kd], b4);
                    mma16816(s[2 * njp + 1], qf[kd], b4 + 2);
                }

            // exp + row sums (no max subtraction; scores safely bounded)
            #pragma unroll
            for (int rs = 0; rs < 2; rs++) {
                float sum = 0.f;
                #pragma unroll
                for (int nj = 0; nj < 8; nj++) {
                    float p0 = fexp2(s[nj][rs * 2] * SC);
                    float p1 = fexp2(s[nj][rs * 2 + 1] * SC);
                    s[nj][rs * 2] = p0;
                    s[nj][rs * 2 + 1] = p1;
                    sum += p0 + p1;
                }
                sum += __shfl_xor_sync(0xffffffffu, sum, 1);
                sum += __shfl_xor_sync(0xffffffffu, sum, 2);
                lrow[rs] += sum;
            }

            // O += P V  (V fragments: x4 trans, two col-groups per instr)
            #pragma unroll
            for (int kk = 0; kk < 4; kk++) {
                uint32_t pa[4];
                pa[0] = packbf(s[2 * kk][0],     s[2 * kk][1]);
                pa[1] = packbf(s[2 * kk][2],     s[2 * kk][3]);
                pa[2] = packbf(s[2 * kk + 1][0], s[2 * kk + 1][1]);
                pa[3] = packbf(s[2 * kk + 1][2], s[2 * kk + 1][3]);
                #pragma unroll
                for (int njp = 0; njp < 4; njp++) {
                    uint32_t b4[4];
                    ldm_x4t(b4, smb + 5 * 32768 +
                            swz((kc * 64 + kk * 16 + (sel & 1) * 8 + li) * 128 +
                                (2 * njp + (sel >> 1)) * 16));
                    mma16816(O[2 * njp],     pa, b4);
                    mma16816(O[2 * njp + 1], pa, b4 + 2);
                }
            }
        }

        // write ctx for this head
        #pragma unroll
        for (int rs = 0; rs < 2; rs++) {
            float inv = 1.f / lrow[rs];
            int row = warp * 16 + rs * 8 + g;
            #pragma unroll
            for (int nj = 0; nj < 8; nj++) {
                int col = nj * 8 + tig * 2;
                *reinterpret_cast<__nv_bfloat162*>(
                    &g_ctx[((size_t)b * NS + row) * ND + h * DH + col]) =
                    __floats2bfloat162_rn(O[nj][rs * 2] * inv, O[nj][rs * 2 + 1] * inv);
            }
        }
    }
}

// ---------------------------------------------------------------------------
// Output projection (R7 config, measured 54.1us): 3-stage cp.async pipeline.
// out = (gsize>1) ? batch_seq + ctx@Wo + bo : batch_seq
// gsize>1 computed inline via ballot.
// ---------------------------------------------------------------------------
__global__ __launch_bounds__(256) void gemm_out(const float* __restrict__ bs,
                                                const int* __restrict__ ids,
                                                const float* __restrict__ bo,
                                                float* __restrict__ out) {
    __shared__ __nv_bfloat16 Asm[3][128][40];
    __shared__ __nv_bfloat16 Bsm[3][32][136];
    __shared__ int s_size;

    const int tid  = threadIdx.x;
    const int lane = tid & 31;
    const int warp = tid >> 5;
    const int wm = warp >> 1, wn = warp & 1;
    const int r0 = tid >> 2, c0 = (tid & 3) * 8;
    const int li = lane & 7, sel = lane >> 3, l16 = lane & 15;

    const int m0 = blockIdx.x * 128;
    const int n0 = blockIdx.y * 128;
    const int b = m0 >> 8;
    const __nv_bfloat16* A = g_ctx + (size_t)m0 * 256;

    // inline group-size: big = (#{j: ids[j]==ids[b]} > 1)
    if (tid == 0) s_size = 0;
    __syncthreads();
    {
        int idb = __ldg(&ids[b]);
        bool same = (__ldg(&ids[tid]) == idb);
        unsigned m = __ballot_sync(0xffffffffu, same);
        if (lane == 0 && m) atomicAdd(&s_size, __popc(m));
    }

    float acc[2][8][4];
    #pragma unroll
    for (int i = 0; i < 2; i++)
        #pragma unroll
        for (int j = 0; j < 8; j++)
            #pragma unroll
            for (int c = 0; c < 4; c++) acc[i][j][c] = 0.f;

    auto stage = [&](int buf, int kt) {
        const __nv_bfloat16* Ag = A + kt * 32;
        cpa16(sptr(&Asm[buf][r0][c0]),      &Ag[r0 * 256 + c0]);
        cpa16(sptr(&Asm[buf][r0 + 64][c0]), &Ag[(r0 + 64) * 256 + c0]);
        int br = tid >> 4, bc = (tid & 15) * 8;
        cpa16(sptr(&Bsm[buf][br][bc]),      &g_Wo[(kt * 32 + br) * ND + n0 + bc]);
        cpa16(sptr(&Bsm[buf][br + 16][bc]), &g_Wo[(kt * 32 + br + 16) * ND + n0 + bc]);
        cpcommit();
    };

    stage(0, 0);
    stage(1, 1);
    #pragma unroll 1
    for (int kt = 0; kt < 8; kt++) {
        const int buf = kt % 3;
        if (kt < 6) {
            stage((kt + 2) % 3, kt + 2);
            cpwait<2>();
        } else if (kt == 6) {
            cpwait<1>();
        } else {
            cpwait<0>();
        }
        __syncthreads();
        #pragma unroll
        for (int ks = 0; ks < 2; ks++) {
            uint32_t a[2][4];
            ldm_x4(a[0], sptr(&Asm[buf][wm * 32 +      li + (sel & 1) * 8][ks * 16 + (sel >> 1) * 8]));
            ldm_x4(a[1], sptr(&Asm[buf][wm * 32 + 16 + li + (sel & 1) * 8][ks * 16 + (sel >> 1) * 8]));
            #pragma unroll
            for (int nj = 0; nj < 8; nj++) {
                uint32_t bfr[2];
                ldm_x2t(bfr, sptr(&Bsm[buf][ks * 16 + l16][wn * 64 + nj * 8]));
                mma16816(acc[0][nj], a[0], bfr);
                mma16816(acc[1][nj], a[1], bfr);
            }
        }
        __syncthreads();
    }

    const int g = lane >> 2, tig = lane & 3;
    const int big = (s_size > 1);
    #pragma unroll
    for (int mi = 0; mi < 2; mi++)
        #pragma unroll
        for (int nj = 0; nj < 8; nj++)
            #pragma unroll
            for (int p = 0; p < 2; p++) {
                int m = m0 + wm * 32 + mi * 16 + p * 8 + g;
                int n = n0 + wn * 64 + nj * 8 + tig * 2;
                int idx = m * ND + n;
                float2 base = *reinterpret_cast<const float2*>(&bs[idx]);
                float2 o;
                if (big) {
                    o.x = base.x + acc[mi][nj][p * 2]     + bo[n];
                    o.y = base.y + acc[mi][nj][p * 2 + 1] + bo[n + 1];
                } else {
                    o = base;
                }
                *reinterpret_cast<float2*>(&out[idx]) = o;
            }
}

// ---------------------------------------------------------------------------
// Launch
// ---------------------------------------------------------------------------
extern "C" void kernel_launch(void* const* d_in, const int* in_sizes, int n_in,
                              void* d_out, int out_size) {
    const float* bs    = (const float*)d_in[0];
    const int*   ids   = (const int*)d_in[1];
    const float* Wq    = (const float*)d_in[2];
    const float* Wk    = (const float*)d_in[3];
    const float* Wv    = (const float*)d_in[4];
    const float* Wo    = (const float*)d_in[5];
    const float* bq    = (const float*)d_in[6];
    const float* bk    = (const float*)d_in[7];
    const float* bv    = (const float*)d_in[8];
    const float* bo    = (const float*)d_in[9];
    const float* obj   = (const float*)d_in[10];
    const float* scale = (const float*)d_in[11];
    const int max_obj = in_sizes[10] / ND;

    static bool configured = false;
    if (!configured) {
        cudaFuncSetAttribute(fused_b, cudaFuncAttributeMaxDynamicSharedMemorySize, FUSED_SMEM);
        configured = true;
    }

    cast_weights<<<256, 256>>>(Wq, Wk, Wv, Wo);
    fused_b<<<NB, 512, FUSED_SMEM>>>(bs, ids, obj, scale, bq, bk, bv, max_obj);
    gemm_out<<<dim3(512, 2), 256>>>(bs, ids, bo, (float*)d_out);
}